// round 15
// baseline (speedup 1.0000x reference)
#include <cuda_runtime.h>
#include <cuda_fp16.h>

#define NNODES 200000
#define AF 82
#define H 10
#define ED 6
#define STRIDE 12     // fp32 h rows: 48B
#define PSTRIDE 16    // fp16 p rows: 32B (halves 10..15 permanent zeros)
#define NPLANES 4
#define APSTRIDE 16   // fp16 agg plane rows: 32B

__device__ float g_h[(size_t)NNODES * STRIDE];
__device__ __half g_p[(size_t)NNODES * PSTRIDE];
__device__ __half g_aggh[(size_t)NPLANES * NNODES * APSTRIDE];   // 25.6MB

__device__ __forceinline__ float lrelu(float x) { return fmaxf(x, 0.1f * x); }

__device__ __forceinline__ void store_p_fp16(__half* pr, const float* pv) {
    __half2 t0 = __floats2half2_rn(pv[0], pv[1]);
    __half2 t1 = __floats2half2_rn(pv[2], pv[3]);
    __half2 t2 = __floats2half2_rn(pv[4], pv[5]);
    __half2 t3 = __floats2half2_rn(pv[6], pv[7]);
    __half2 t4 = __floats2half2_rn(pv[8], pv[9]);
    uint4 q;
    q.x = *(unsigned*)&t0; q.y = *(unsigned*)&t1;
    q.z = *(unsigned*)&t2; q.w = *(unsigned*)&t3;
    *(uint4*)pr = q;
    uint4 q2;
    q2.x = *(unsigned*)&t4; q2.y = 0u; q2.z = 0u; q2.w = 0u;
    *(uint4*)(pr + 8) = q2;
}

// ---------------------------------------------------------------------------
// init v2: 2 lanes per node. Pair lanes split the row's 41 float2 chunks
// (chunk c handled by role c&1), butterfly-combine partial acc via shfl_xor,
// role0 stores h, role1 stores p; roles split plane-zeroing.
// ---------------------------------------------------------------------------
__global__ void init_kernel(const float* __restrict__ vertex,
                            const float* __restrict__ Wi,
                            const float* __restrict__ Wg, int n) {
    __shared__ float wi[AF * H];
    __shared__ float wg[H * H];
    for (int i = threadIdx.x; i < AF * H; i += blockDim.x) wi[i] = Wi[i];
    for (int i = threadIdx.x; i < H * H; i += blockDim.x) wg[i] = Wg[i];
    __syncthreads();

    int lane_id = blockIdx.x * blockDim.x + threadIdx.x;
    int node = lane_id >> 1;
    int role = lane_id & 1;
    if (node >= n) node = n - 1;   // clamp: redundant lanes redo last node (benign)

    // zero this role's half of the agg planes (layer-0 prep)
    {
        uint4 z = make_uint4(0, 0, 0, 0);
#pragma unroll
        for (int pl = 0; pl < NPLANES / 2; pl++) {
            int p = role * (NPLANES / 2) + pl;
            __half* ar = g_aggh + ((size_t)p * NNODES + node) * APSTRIDE;
            ((uint4*)ar)[0] = z;
            ((uint4*)ar)[1] = z;
        }
    }

    const float2* row2 = (const float2*)(vertex + (size_t)node * AF);  // 8B-aligned (328B rows)
    float acc[H];
#pragma unroll
    for (int j = 0; j < H; j++) acc[j] = 0.f;

    // chunks c = role, role+2, ..., covering features 2c, 2c+1.
    // role0: c = 0,2,...,40 (21 chunks); role1: c = 1,3,...,39 (20 chunks)
#pragma unroll
    for (int i = 0; i < 21; i++) {
        int c = 2 * i + role;
        if (role == 1 && i == 20) break;   // role1 has 20 chunks
        float2 v = row2[c];
        const float* wk = wi + (2 * c) * H;
#pragma unroll
        for (int j = 0; j < H; j++)
            acc[j] += v.x * wk[j] + v.y * wk[H + j];
    }

    // butterfly: combine partial sums across the lane pair
#pragma unroll
    for (int j = 0; j < H; j++)
        acc[j] += __shfl_xor_sync(0xFFFFFFFFu, acc[j], 1);

    float h[H];
#pragma unroll
    for (int j = 0; j < H; j++) h[j] = lrelu(acc[j]);

    if (role == 0) {
        float4* hw = (float4*)(g_h + (size_t)node * STRIDE);
        hw[0] = make_float4(h[0], h[1], h[2], h[3]);
        hw[1] = make_float4(h[4], h[5], h[6], h[7]);
        hw[2] = make_float4(h[8], h[9], 0.f, 0.f);
    } else {
        float pv[H];
#pragma unroll
        for (int j = 0; j < H; j++) {
            float a = 0.f;
#pragma unroll
            for (int i = 0; i < H; i++) a += h[i] * wg[i * H + j];
            pv[j] = a;
        }
        store_p_fp16(g_p + (size_t)node * PSTRIDE, pv);
    }
}

// ---------------------------------------------------------------------------
// edge: 2 lanes per edge (role = tid&1). Each lane: one LDG.128 p-gather of
// its 16B half-row, 8 output dims, one red.v4.f16x2 into its 16B half of the
// agg row (plane = e&3). Proven R7/R13 structure — frozen.
// ---------------------------------------------------------------------------
__global__ void __launch_bounds__(256, 8)
edge_kernel(const float* __restrict__ ef,
            const int* __restrict__ src,
            const int* __restrict__ dst,
            const float* __restrict__ Wg, int ecnt) {
    __shared__ float wpad[ED][16];
    for (int i = threadIdx.x; i < ED * 16; i += blockDim.x) {
        int k = i >> 4, j = i & 15;
        wpad[k][j] = (j < H) ? Wg[(H + k) * H + j] : 0.f;
    }
    __syncthreads();

    int tid = blockIdx.x * blockDim.x + threadIdx.x;
    int e = tid >> 1;
    int role = tid & 1;
    if (e >= ecnt) return;

    int s = src[e];
    int d = dst[e];

    const float2* ep = (const float2*)(ef + (size_t)e * ED);
    float2 f0 = ep[0], f1 = ep[1], f2 = ep[2];
    float ev[ED] = {f0.x, f0.y, f1.x, f1.y, f2.x, f2.y};

    const __half* pr = g_p + (size_t)s * PSTRIDE + role * 8;
    uint4 q = *(const uint4*)pr;
    float pl[8];
    {
        float2 f;
        f = __half22float2(*(__half2*)&q.x); pl[0] = f.x; pl[1] = f.y;
        f = __half22float2(*(__half2*)&q.y); pl[2] = f.x; pl[3] = f.y;
        f = __half22float2(*(__half2*)&q.z); pl[4] = f.x; pl[5] = f.y;
        f = __half22float2(*(__half2*)&q.w); pl[6] = f.x; pl[7] = f.y;
    }

    const float* wj = &wpad[0][role * 8];
    float m[8];
#pragma unroll
    for (int jj = 0; jj < 8; jj++) {
        float a = pl[jj];
#pragma unroll
        for (int k = 0; k < ED; k++) a += ev[k] * wj[k * 16 + jj];
        m[jj] = lrelu(a);
    }

    __half2 h0 = __floats2half2_rn(m[0], m[1]);
    __half2 h1 = __floats2half2_rn(m[2], m[3]);
    __half2 h2 = __floats2half2_rn(m[4], m[5]);
    __half2 h3 = __floats2half2_rn(m[6], m[7]);

    int plane = e & (NPLANES - 1);
    __half* ap = g_aggh + ((size_t)plane * NNODES + d) * APSTRIDE + role * 8;
    asm volatile("red.global.add.noftz.v4.f16x2 [%0], {%1,%2,%3,%4};" ::
                 "l"(ap), "r"(*(unsigned*)&h0), "r"(*(unsigned*)&h1),
                 "r"(*(unsigned*)&h2), "r"(*(unsigned*)&h3) : "memory");
}

// ---------------------------------------------------------------------------
// update: agg = sum of 4 fp16 planes; h' = lrelu([h,agg] @ Wu);
// layer 0: also write p' and re-zero planes for next layer
// ---------------------------------------------------------------------------
__global__ void update_kernel(const float* __restrict__ Wu,
                              const float* __restrict__ Wg,
                              float* __restrict__ out, int n,
                              int out_stride, int write_p) {
    __shared__ float wu[2 * H * H];
    __shared__ float wg[H * H];
    for (int i = threadIdx.x; i < 2 * H * H; i += blockDim.x) wu[i] = Wu[i];
    for (int i = threadIdx.x; i < H * H; i += blockDim.x) wg[i] = Wg[i];
    __syncthreads();

    int node = blockIdx.x * blockDim.x + threadIdx.x;
    if (node >= n) return;

    size_t off = (size_t)node * STRIDE;
    const float4* hr = (const float4*)(g_h + off);
    float4 h0 = hr[0], h1 = hr[1], h2 = hr[2];
    float hv[H] = {h0.x, h0.y, h0.z, h0.w, h1.x, h1.y, h1.z, h1.w, h2.x, h2.y};

    float av[H];
#pragma unroll
    for (int j = 0; j < H; j++) av[j] = 0.f;
#pragma unroll
    for (int pl = 0; pl < NPLANES; pl++) {
        const __half* ar = g_aggh + ((size_t)pl * NNODES + node) * APSTRIDE;
        uint4 q = *(const uint4*)ar;
        unsigned t = *(const unsigned*)(ar + 8);
        float2 f;
        f = __half22float2(*(__half2*)&q.x); av[0] += f.x; av[1] += f.y;
        f = __half22float2(*(__half2*)&q.y); av[2] += f.x; av[3] += f.y;
        f = __half22float2(*(__half2*)&q.z); av[4] += f.x; av[5] += f.y;
        f = __half22float2(*(__half2*)&q.w); av[6] += f.x; av[7] += f.y;
        f = __half22float2(*(__half2*)&t);   av[8] += f.x; av[9] += f.y;
    }

    if (write_p) {   // prep planes for next layer
        uint4 z = make_uint4(0, 0, 0, 0);
#pragma unroll
        for (int pl = 0; pl < NPLANES; pl++) {
            __half* ar = g_aggh + ((size_t)pl * NNODES + node) * APSTRIDE;
            ((uint4*)ar)[0] = z;
            ((uint4*)ar)[1] = z;
        }
    }

    float o[H];
#pragma unroll
    for (int j = 0; j < H; j++) {
        float a = 0.f;
#pragma unroll
        for (int i = 0; i < H; i++) a += hv[i] * wu[i * H + j];
#pragma unroll
        for (int i = 0; i < H; i++) a += av[i] * wu[(H + i) * H + j];
        o[j] = lrelu(a);
    }

    if (out_stride == STRIDE) {
        float4* ow = (float4*)(out + (size_t)node * STRIDE);
        ow[0] = make_float4(o[0], o[1], o[2], o[3]);
        ow[1] = make_float4(o[4], o[5], o[6], o[7]);
        ow[2] = make_float4(o[8], o[9], 0.f, 0.f);
    } else {
        float2* ow = (float2*)(out + (size_t)node * H);
#pragma unroll
        for (int j = 0; j < H / 2; j++) ow[j] = make_float2(o[2 * j], o[2 * j + 1]);
    }

    if (write_p) {
        float pv[H];
#pragma unroll
        for (int j = 0; j < H; j++) {
            float a = 0.f;
#pragma unroll
            for (int i = 0; i < H; i++) a += o[i] * wg[i * H + j];
            pv[j] = a;
        }
        store_p_fp16(g_p + (size_t)node * PSTRIDE, pv);
    }
}

// ---------------------------------------------------------------------------
extern "C" void kernel_launch(void* const* d_in, const int* in_sizes, int n_in,
                              void* d_out, int out_size) {
    const float* vertex = (const float*)d_in[0];
    const float* ef = (const float*)d_in[1];
    const int* src = (const int*)d_in[2];
    const int* dst = (const int*)d_in[3];
    const float* Wi = (const float*)d_in[4];
    const float* Wg = (const float*)d_in[5];
    const float* Wu = (const float*)d_in[6];
    float* out = (float*)d_out;

    int n = in_sizes[0] / AF;
    int e = in_sizes[2];

    void* hp = nullptr;
    cudaGetSymbolAddress(&hp, g_h);

    int nb = (n + 255) / 256;
    long long nlanes = 2LL * n;
    int ib = (int)((nlanes + 255) / 256);
    long long elanes = 2LL * e;
    int eb = (int)((elanes + 255) / 256);

    init_kernel<<<ib, 256>>>(vertex, Wi, Wg, n);
    for (int l = 0; l < 2; l++) {
        edge_kernel<<<eb, 256>>>(ef, src, dst, Wg, e);
        update_kernel<<<nb, 256>>>(Wu, Wg, (l == 1) ? out : (float*)hp, n,
                                   (l == 1) ? H : STRIDE, (l == 0) ? 1 : 0);
    }
}

// round 17
// speedup vs baseline: 1.0265x; 1.0265x over previous
#include <cuda_runtime.h>
#include <cuda_fp16.h>

#define NNODES 200000
#define AF 82
#define H 10
#define ED 6
#define STRIDE 12     // fp32 h rows: 48B
#define PSTRIDE 16    // fp16 p rows: 32B (halves 10..15 permanent zeros)
#define NPLANES 4
#define APSTRIDE 16   // fp16 agg plane rows: 32B

__device__ float g_h[(size_t)NNODES * STRIDE];
__device__ __half g_p[(size_t)NNODES * PSTRIDE];
__device__ __half g_aggh[(size_t)NPLANES * NNODES * APSTRIDE];   // 25.6MB

__device__ __forceinline__ float lrelu(float x) { return fmaxf(x, 0.1f * x); }

__device__ __forceinline__ void store_p_fp16(__half* pr, const float* pv) {
    __half2 t0 = __floats2half2_rn(pv[0], pv[1]);
    __half2 t1 = __floats2half2_rn(pv[2], pv[3]);
    __half2 t2 = __floats2half2_rn(pv[4], pv[5]);
    __half2 t3 = __floats2half2_rn(pv[6], pv[7]);
    __half2 t4 = __floats2half2_rn(pv[8], pv[9]);
    uint4 q;
    q.x = *(unsigned*)&t0; q.y = *(unsigned*)&t1;
    q.z = *(unsigned*)&t2; q.w = *(unsigned*)&t3;
    *(uint4*)pr = q;
    uint4 q2;
    q2.x = *(unsigned*)&t4; q2.y = 0u; q2.z = 0u; q2.w = 0u;
    *(uint4*)(pr + 8) = q2;
}

__device__ __forceinline__ void zero_planes(int node) {
    uint4 z = make_uint4(0, 0, 0, 0);
#pragma unroll
    for (int pl = 0; pl < NPLANES; pl++) {
        __half* ar = g_aggh + ((size_t)pl * NNODES + node) * APSTRIDE;
        ((uint4*)ar)[0] = z;
        ((uint4*)ar)[1] = z;
    }
}

// ---------------------------------------------------------------------------
// init: h = lrelu(vertex @ Wi); p = h @ Wg_top; zero agg planes (layer-0 prep)
// R13 form (proven). Reads only harness inputs — no grid dependency.
// ---------------------------------------------------------------------------
__global__ void init_kernel(const float* __restrict__ vertex,
                            const float* __restrict__ Wi,
                            const float* __restrict__ Wg, int n) {
    __shared__ float wi[AF * H];
    __shared__ float wg[H * H];
    for (int i = threadIdx.x; i < AF * H; i += blockDim.x) wi[i] = Wi[i];
    for (int i = threadIdx.x; i < H * H; i += blockDim.x) wg[i] = Wg[i];
    __syncthreads();
    int node = blockIdx.x * blockDim.x + threadIdx.x;
    if (node >= n) return;

    zero_planes(node);

    const float* row = vertex + (size_t)node * AF;
    float acc[H];
#pragma unroll
    for (int j = 0; j < H; j++) acc[j] = 0.f;

    int base = (node & 1) ? 2 : 0;
    if (node & 1) {
        float2 hd = *(const float2*)row;
#pragma unroll
        for (int j = 0; j < H; j++)
            acc[j] += hd.x * wi[0 * H + j] + hd.y * wi[1 * H + j];
    }
    const float4* r4 = (const float4*)(row + base);
    const float* wb = wi + base * H;
#pragma unroll
    for (int i = 0; i < 20; i++) {
        float4 v = r4[i];
        const float* wk = wb + (4 * i) * H;
#pragma unroll
        for (int j = 0; j < H; j++)
            acc[j] += v.x * wk[j] + v.y * wk[H + j] +
                      v.z * wk[2 * H + j] + v.w * wk[3 * H + j];
    }
    if (!(node & 1)) {
        float2 tl = *(const float2*)(row + 80);
#pragma unroll
        for (int j = 0; j < H; j++)
            acc[j] += tl.x * wi[80 * H + j] + tl.y * wi[81 * H + j];
    }

    float h[H];
#pragma unroll
    for (int j = 0; j < H; j++) h[j] = lrelu(acc[j]);

    float pv[H];
#pragma unroll
    for (int j = 0; j < H; j++) {
        float a = 0.f;
#pragma unroll
        for (int i = 0; i < H; i++) a += h[i] * wg[i * H + j];
        pv[j] = a;
    }

    float4* hw = (float4*)(g_h + (size_t)node * STRIDE);
    hw[0] = make_float4(h[0], h[1], h[2], h[3]);
    hw[1] = make_float4(h[4], h[5], h[6], h[7]);
    hw[2] = make_float4(h[8], h[9], 0.f, 0.f);
    store_p_fp16(g_p + (size_t)node * PSTRIDE, pv);
}

// ---------------------------------------------------------------------------
// edge (PDL): prologue = weights->smem + streaming ef/idx (harness inputs,
// dependency-free). cudaGridDependencySynchronize() BEFORE touching g_p /
// g_aggh (written by predecessor grid). Frozen R7/R13 memory structure.
// ---------------------------------------------------------------------------
__global__ void __launch_bounds__(256, 8)
edge_kernel(const float* __restrict__ ef,
            const int* __restrict__ src,
            const int* __restrict__ dst,
            const float* __restrict__ Wg, int ecnt) {
    __shared__ float wpad[ED][16];
    for (int i = threadIdx.x; i < ED * 16; i += blockDim.x) {
        int k = i >> 4, j = i & 15;
        wpad[k][j] = (j < H) ? Wg[(H + k) * H + j] : 0.f;
    }
    __syncthreads();

    int tid = blockIdx.x * blockDim.x + threadIdx.x;
    int e = tid >> 1;
    int role = tid & 1;
    if (e >= ecnt) return;

    int s = src[e];
    int d = dst[e];

    const float2* ep = (const float2*)(ef + (size_t)e * ED);
    float2 f0 = ep[0], f1 = ep[1], f2 = ep[2];
    float ev[ED] = {f0.x, f0.y, f1.x, f1.y, f2.x, f2.y};

    // wait for predecessor grid (init or update0): p rows + zeroed planes
    cudaGridDependencySynchronize();

    const __half* pr = g_p + (size_t)s * PSTRIDE + role * 8;
    uint4 q = *(const uint4*)pr;
    float pl[8];
    {
        float2 f;
        f = __half22float2(*(__half2*)&q.x); pl[0] = f.x; pl[1] = f.y;
        f = __half22float2(*(__half2*)&q.y); pl[2] = f.x; pl[3] = f.y;
        f = __half22float2(*(__half2*)&q.z); pl[4] = f.x; pl[5] = f.y;
        f = __half22float2(*(__half2*)&q.w); pl[6] = f.x; pl[7] = f.y;
    }

    const float* wj = &wpad[0][role * 8];
    float m[8];
#pragma unroll
    for (int jj = 0; jj < 8; jj++) {
        float a = pl[jj];
#pragma unroll
        for (int k = 0; k < ED; k++) a += ev[k] * wj[k * 16 + jj];
        m[jj] = lrelu(a);
    }

    __half2 h0 = __floats2half2_rn(m[0], m[1]);
    __half2 h1 = __floats2half2_rn(m[2], m[3]);
    __half2 h2 = __floats2half2_rn(m[4], m[5]);
    __half2 h3 = __floats2half2_rn(m[6], m[7]);

    int plane = e & (NPLANES - 1);
    __half* ap = g_aggh + ((size_t)plane * NNODES + d) * APSTRIDE + role * 8;
    asm volatile("red.global.add.noftz.v4.f16x2 [%0], {%1,%2,%3,%4};" ::
                 "l"(ap), "r"(*(unsigned*)&h0), "r"(*(unsigned*)&h1),
                 "r"(*(unsigned*)&h2), "r"(*(unsigned*)&h3) : "memory");
}

// ---------------------------------------------------------------------------
// update (PDL): prologue = weights->smem only. griddepsync before reading
// g_h / g_aggh (h written 2 grids back — covered transitively: every live CTA
// of the predecessor edge grid synced on the grid before it).
// ---------------------------------------------------------------------------
__global__ void update_kernel(const float* __restrict__ Wu,
                              const float* __restrict__ Wg,
                              float* __restrict__ out, int n,
                              int out_stride, int write_p) {
    __shared__ float wu[2 * H * H];
    __shared__ float wg[H * H];
    for (int i = threadIdx.x; i < 2 * H * H; i += blockDim.x) wu[i] = Wu[i];
    for (int i = threadIdx.x; i < H * H; i += blockDim.x) wg[i] = Wg[i];
    __syncthreads();

    int node = blockIdx.x * blockDim.x + threadIdx.x;
    if (node >= n) return;

    cudaGridDependencySynchronize();

    size_t off = (size_t)node * STRIDE;
    const float4* hr = (const float4*)(g_h + off);
    float4 h0 = hr[0], h1 = hr[1], h2 = hr[2];
    float hv[H] = {h0.x, h0.y, h0.z, h0.w, h1.x, h1.y, h1.z, h1.w, h2.x, h2.y};

    float av[H];
#pragma unroll
    for (int j = 0; j < H; j++) av[j] = 0.f;
#pragma unroll
    for (int pl = 0; pl < NPLANES; pl++) {
        const __half* ar = g_aggh + ((size_t)pl * NNODES + node) * APSTRIDE;
        uint4 q = *(const uint4*)ar;
        unsigned t = *(const unsigned*)(ar + 8);
        float2 f;
        f = __half22float2(*(__half2*)&q.x); av[0] += f.x; av[1] += f.y;
        f = __half22float2(*(__half2*)&q.y); av[2] += f.x; av[3] += f.y;
        f = __half22float2(*(__half2*)&q.z); av[4] += f.x; av[5] += f.y;
        f = __half22float2(*(__half2*)&q.w); av[6] += f.x; av[7] += f.y;
        f = __half22float2(*(__half2*)&t);   av[8] += f.x; av[9] += f.y;
    }

    if (write_p) zero_planes(node);   // prep planes for next layer

    float o[H];
#pragma unroll
    for (int j = 0; j < H; j++) {
        float a = 0.f;
#pragma unroll
        for (int i = 0; i < H; i++) a += hv[i] * wu[i * H + j];
#pragma unroll
        for (int i = 0; i < H; i++) a += av[i] * wu[(H + i) * H + j];
        o[j] = lrelu(a);
    }

    if (out_stride == STRIDE) {
        float4* ow = (float4*)(out + (size_t)node * STRIDE);
        ow[0] = make_float4(o[0], o[1], o[2], o[3]);
        ow[1] = make_float4(o[4], o[5], o[6], o[7]);
        ow[2] = make_float4(o[8], o[9], 0.f, 0.f);
    } else {
        float2* ow = (float2*)(out + (size_t)node * H);
#pragma unroll
        for (int j = 0; j < H / 2; j++) ow[j] = make_float2(o[2 * j], o[2 * j + 1]);
    }

    if (write_p) {
        float pv[H];
#pragma unroll
        for (int j = 0; j < H; j++) {
            float a = 0.f;
#pragma unroll
            for (int i = 0; i < H; i++) a += o[i] * wg[i * H + j];
            pv[j] = a;
        }
        store_p_fp16(g_p + (size_t)node * PSTRIDE, pv);
    }
}

// ---------------------------------------------------------------------------
static void launch_pdl(void* func, dim3 grid, dim3 block, void** args) {
    cudaLaunchConfig_t cfg = {};
    cfg.gridDim = grid;
    cfg.blockDim = block;
    cfg.stream = 0;
    cudaLaunchAttribute attr[1];
    attr[0].id = cudaLaunchAttributeProgrammaticStreamSerialization;
    attr[0].val.programmaticStreamSerializationAllowed = 1;
    cfg.attrs = attr;
    cfg.numAttrs = 1;
    cudaLaunchKernelExC(&cfg, func, args);
}

extern "C" void kernel_launch(void* const* d_in, const int* in_sizes, int n_in,
                              void* d_out, int out_size) {
    const float* vertex = (const float*)d_in[0];
    const float* ef = (const float*)d_in[1];
    const int* src = (const int*)d_in[2];
    const int* dst = (const int*)d_in[3];
    const float* Wi = (const float*)d_in[4];
    const float* Wg = (const float*)d_in[5];
    const float* Wu = (const float*)d_in[6];
    float* out = (float*)d_out;

    int n = in_sizes[0] / AF;
    int e = in_sizes[2];

    void* hp = nullptr;
    cudaGetSymbolAddress(&hp, g_h);

    int nb = (n + 255) / 256;
    long long elanes = 2LL * e;
    int eb = (int)((elanes + 255) / 256);

    init_kernel<<<nb, 256>>>(vertex, Wi, Wg, n);

    for (int l = 0; l < 2; l++) {
        {
            void* args[] = {(void*)&ef, (void*)&src, (void*)&dst, (void*)&Wg,
                            (void*)&e};
            launch_pdl((void*)edge_kernel, dim3(eb), dim3(256), args);
        }
        {
            float* uout = (l == 1) ? out : (float*)hp;
            int ostride = (l == 1) ? H : STRIDE;
            int wp = (l == 0) ? 1 : 0;
            void* args[] = {(void*)&Wu, (void*)&Wg, (void*)&uout, (void*)&n,
                            (void*)&ostride, (void*)&wp};
            launch_pdl((void*)update_kernel, dim3(nb), dim3(256), args);
        }
    }
}